// round 1
// baseline (speedup 1.0000x reference)
#include <cuda_runtime.h>
#include <cstdint>

// Attention: softmax(Q K^T) V, unscaled, unmasked.
// B=4, H=16, S=2048, D=64, fp32.
// Flash-attention style, one thread per query row, packed f32x2 FMA.

#define BHEADS 64      // B*H
#define SEQ    2048
#define HD     64
#define BM     128     // query rows per block == threads per block
#define BN     32      // keys per smem tile
#define NTILES (SEQ / BN)

typedef unsigned long long u64;

__device__ __forceinline__ u64 fma2(u64 a, u64 b, u64 c) {
    u64 d;
    asm("fma.rn.f32x2 %0, %1, %2, %3;" : "=l"(d) : "l"(a), "l"(b), "l"(c));
    return d;
}
__device__ __forceinline__ u64 mul2(u64 a, u64 b) {
    u64 d;
    asm("mul.rn.f32x2 %0, %1, %2;" : "=l"(d) : "l"(a), "l"(b));
    return d;
}
__device__ __forceinline__ u64 pack2(float lo, float hi) {
    u64 d;
    asm("mov.b64 %0, {%1, %2};" : "=l"(d) : "f"(lo), "f"(hi));
    return d;
}
__device__ __forceinline__ float hsum2(u64 a) {
    float lo, hi;
    asm("mov.b64 {%0, %1}, %2;" : "=f"(lo), "=f"(hi) : "l"(a));
    return lo + hi;
}

__global__ __launch_bounds__(BM, 2)
void attn_flash_f32x2(const float* __restrict__ Q,
                      const float* __restrict__ K,
                      const float* __restrict__ V,
                      float* __restrict__ O) {
    __shared__ __align__(16) float sK[BN * HD];
    __shared__ __align__(16) float sV[BN * HD];

    const int head = blockIdx.y;                       // 0..63  (b*H + h)
    const int row  = blockIdx.x * BM + threadIdx.x;    // query row in sequence

    const size_t head_base = (size_t)head * SEQ * HD;

    // Load this thread's q row as 32 packed f32x2.
    u64 q2[HD / 2];
    {
        const u64* qp = (const u64*)(Q + head_base + (size_t)row * HD);
        #pragma unroll
        for (int i = 0; i < HD / 2; ++i) q2[i] = qp[i];
    }

    // Output accumulator (unnormalized), packed f32x2. 0ull == (0.0f, 0.0f).
    u64 o2[HD / 2];
    #pragma unroll
    for (int i = 0; i < HD / 2; ++i) o2[i] = 0ull;

    float m = -1e30f;   // running max
    float l = 0.0f;     // running sum

    const float* kbase = K + head_base;
    const float* vbase = V + head_base;

    for (int t = 0; t < NTILES; ++t) {
        __syncthreads();   // previous tile fully consumed
        // Cooperative tile load: BN*HD = 2048 floats = 512 float4; 4 per thread.
        {
            const float4* kg = (const float4*)(kbase + (size_t)t * BN * HD);
            const float4* vg = (const float4*)(vbase + (size_t)t * BN * HD);
            float4* sk4 = (float4*)sK;
            float4* sv4 = (float4*)sV;
            #pragma unroll
            for (int i = 0; i < (BN * HD / 4) / BM; ++i) {
                int idx = threadIdx.x + i * BM;
                sk4[idx] = kg[idx];
                sv4[idx] = vg[idx];
            }
        }
        __syncthreads();

        // ---- QK^T: 32 scores for this row ----
        float s[BN];
        #pragma unroll
        for (int j = 0; j < BN; ++j) {
            const ulonglong2* krow = (const ulonglong2*)(sK + j * HD);
            u64 acc_a = 0ull, acc_b = 0ull;   // two chains to hide FMA latency
            #pragma unroll
            for (int i = 0; i < HD / 4; ++i) {
                ulonglong2 kk = krow[i];              // LDS.128 broadcast
                acc_a = fma2(q2[2 * i + 0], kk.x, acc_a);
                acc_b = fma2(q2[2 * i + 1], kk.y, acc_b);
            }
            s[j] = hsum2(acc_a) + hsum2(acc_b);
        }

        // ---- online softmax update ----
        float tmax = s[0];
        #pragma unroll
        for (int j = 1; j < BN; ++j) tmax = fmaxf(tmax, s[j]);
        float mnew = fmaxf(m, tmax);
        float corr = __expf(m - mnew);       // first tile: exp(-huge) = 0
        l *= corr;
        u64 c2 = pack2(corr, corr);
        #pragma unroll
        for (int i = 0; i < HD / 2; ++i) o2[i] = mul2(o2[i], c2);

        // ---- P·V accumulate ----
        #pragma unroll
        for (int j = 0; j < BN; ++j) {
            float p = __expf(s[j] - mnew);
            l += p;
            u64 p2 = pack2(p, p);
            const ulonglong2* vrow = (const ulonglong2*)(sV + j * HD);
            #pragma unroll
            for (int i = 0; i < HD / 4; ++i) {
                ulonglong2 vv = vrow[i];              // LDS.128 broadcast
                o2[2 * i + 0] = fma2(p2, vv.x, o2[2 * i + 0]);
                o2[2 * i + 1] = fma2(p2, vv.y, o2[2 * i + 1]);
            }
        }
        m = mnew;
    }

    // Normalize and write out.
    float inv = 1.0f / l;
    u64 inv2 = pack2(inv, inv);
    u64* op = (u64*)(O + head_base + (size_t)row * HD);
    #pragma unroll
    for (int i = 0; i < HD / 2; ++i) op[i] = mul2(o2[i], inv2);
}

extern "C" void kernel_launch(void* const* d_in, const int* in_sizes, int n_in,
                              void* d_out, int out_size) {
    const float* Q = (const float*)d_in[0];
    const float* K = (const float*)d_in[1];
    const float* V = (const float*)d_in[2];
    float* O = (float*)d_out;

    dim3 grid(SEQ / BM, BHEADS);
    dim3 block(BM);
    attn_flash_f32x2<<<grid, block>>>(Q, K, V, O);
}